// round 13
// baseline (speedup 1.0000x reference)
#include <cuda_runtime.h>
#include <cuda_bf16.h>
#include <math.h>
#include <stdint.h>

// ---------------- problem sizes ----------------
#define NMS_N   256
#define HW      16384          // 128*128
#define WORDS   512            // 16384/32
#define NB      64             // batch for CRF
#define NPIX    (NB*HW)        // 1,048,576

// ---------------- persistent CRF config ----------------
#define CL      4              // cluster size (CTAs per image)
#define RPC     32             // rows per CTA
#define NTHR    1024           // threads per CTA
#define W136    136            // padded row stride (4 left, 4 right pad)
#define PLW3    ((RPC+1)*W136) // weight plane: halo row 0 + RPC rows
#define PLS     ((RPC+2)*W136) // state plane: halo + RPC + halo
#define SMF     (3*PLW3 + 2*PLS)   // floats of dynamic smem

// ---------------- device scratch (static, no allocation) ----------------
__device__ unsigned int g_packed[NMS_N * WORDS];   // [mask][word]
__device__ float        g_sums[NMS_N];
__device__ float        g_dmat[NMS_N * NMS_N];
__device__ float        g_comp[NMS_N];
__device__ int          g_cnt[NB];                 // count | (arrivals<<20)

// ================= helpers =================

__device__ __forceinline__ void cluster_sync_() {
    asm volatile("barrier.cluster.arrive.aligned;" ::: "memory");
    asm volatile("barrier.cluster.wait.aligned;" ::: "memory");
}

__device__ __forceinline__ void st_peer_f32(uint32_t local_addr, uint32_t peer_rank, float v) {
    uint32_t rem;
    asm volatile("mapa.shared::cluster.u32 %0, %1, %2;"
                 : "=r"(rem) : "r"(local_addr), "r"(rem) : );
}

// (real implementation below; the stub above is unused)
__device__ __forceinline__ void st_peer(uint32_t local_addr, uint32_t peer_rank, float v) {
    uint32_t rem;
    asm volatile("mapa.shared::cluster.u32 %0, %1, %2;"
                 : "=r"(rem) : "r"(local_addr), "r"(peer_rank));
    asm volatile("st.shared::cluster.f32 [%0], %1;" :: "r"(rem), "f"(v) : "memory");
}

// ================= NMS =================

__global__ void pack_kernel(const float* __restrict__ seg) {
    int m   = blockIdx.x;
    int tid = threadIdx.x;         // 512 threads
    int warp = tid >> 5, lane = tid & 31;
    int cnt = 0;
    for (int w = warp; w < WORDS; w += 16) {
        float v = seg[(size_t)m * HW + w * 32 + lane];
        unsigned bal = __ballot_sync(0xffffffffu, v != 0.0f);
        if (lane == 0) {
            g_packed[m * WORDS + w] = bal;
            cnt += __popc(bal);
        }
    }
    __shared__ int scnt[16];
    if (lane == 0) scnt[warp] = cnt;
    __syncthreads();
    if (tid == 0) {
        int t = 0;
        for (int i = 0; i < 16; ++i) t += scnt[i];
        g_sums[m] = (float)t;
    }
}

__global__ void nms_iou_kernel(const int* __restrict__ labels) {
    int j = blockIdx.x;
    int i = threadIdx.x;
    __shared__ uint4 smj[WORDS / 4];
    if (i < WORDS / 4)
        smj[i] = ((const uint4*)(g_packed + (size_t)j * WORDS))[i];
    __syncthreads();

    float d = 0.0f;
    if (i < j && labels[i] == labels[j]) {
        const uint4* mi = (const uint4*)(g_packed + (size_t)i * WORDS);
        int inter = 0;
        #pragma unroll 8
        for (int w = 0; w < WORDS / 4; ++w) {
            uint4 a = mi[w];
            uint4 b = smj[w];
            inter += __popc(a.x & b.x) + __popc(a.y & b.y)
                   + __popc(a.z & b.z) + __popc(a.w & b.w);
        }
        float fi  = (float)inter;
        float uni = g_sums[j] + g_sums[i] - fi;
        d = fi / uni;
    }
    g_dmat[j * NMS_N + i] = d;

    __shared__ float red[NMS_N];
    red[i] = d;
    __syncthreads();
    for (int s = NMS_N / 2; s > 0; s >>= 1) {
        if (i < s) red[i] = fmaxf(red[i], red[i + s]);
        __syncthreads();
    }
    if (i == 0) g_comp[j] = red[0];
}

__global__ void nms_coef_kernel(const float* __restrict__ cate_scores,
                                float* __restrict__ out_scores) {
    int j = blockIdx.x;
    int i = threadIdx.x;
    float d  = g_dmat[j * NMS_N + i];
    float ci = g_comp[i];
    float v  = expf(-2.0f * d * d) / expf(-2.0f * ci * ci);
    __shared__ float red[NMS_N];
    red[i] = v;
    __syncthreads();
    for (int s = NMS_N / 2; s > 0; s >>= 1) {
        if (i < s) red[i] = fminf(red[i], red[i + s]);
        __syncthreads();
    }
    if (i == 0) out_scores[j] = cate_scores[j] * red[0];
}

// ================= persistent CRF (+ fused valid) =================
// Cluster of 4 CTAs per image, 32 rows each, 1024 threads, 4 px/thread.
// Only S/SE/SW/E (+W0) weights are computed (17 expf); N/NW/NE are the
// bitwise-identical mirrors fetched from the row above via smem planes.

__global__ void __cluster_dims__(CL, 1, 1) __launch_bounds__(NTHR, 1)
crf_persistent(const float* __restrict__ fm,
               const float* __restrict__ x, const float* __restrict__ tg,
               float* __restrict__ out_masks, float* __restrict__ out_valid) {
    extern __shared__ float sm[];
    __shared__ int red2[32];
    float* pS  = sm;               // plane row q = S/SE/SW of local row q-1
    float* pSE = sm + PLW3;
    float* pSW = sm + 2 * PLW3;
    float* st0 = sm + 3 * PLW3;
    float* st1 = st0 + PLS;

    int t  = threadIdx.x;          // 1024
    int b  = blockIdx.x >> 2;
    uint32_t r = blockIdx.x & 3;
    int tr   = t >> 5;             // 0..31 local row (one warp per row)
    int lane = t & 31;
    int c    = lane << 2;          // 0..124 col base
    int gr = (int)r * RPC + tr;
    size_t gp = (size_t)b * HW + (size_t)gr * 128 + c;
    int so = (tr + 1) * W136 + 4 + c;

    for (int i = t; i < SMF; i += NTHR) sm[i] = 0.0f;

    if (r == 0 && t == 0) {        // reset per-image counter (graph replay safe)
        g_cnt[b] = 0;
        __threadfence();
    }

    // ---- compute S/SE/SW/E/W0 weights (own + south feature rows only) ----
    float wE[4], wW0, wS[4], wSE[4], wSW[4];
    {
        const float* fb = fm + (size_t)b * 3 * HW;
        float sE[4], sW0, sS[4], sSEa[4], sSWa[4];
        bool rin = (gr < 127);
        #pragma unroll
        for (int ch = 0; ch < 3; ++ch) {
            const float* base = fb + (size_t)ch * HW;
            float o6[6], s6[6];
            {   // own row gr, cols c-1..c+4
                size_t rp = (size_t)gr * 128 + c;
                float4 v = *(const float4*)(base + rp);
                float lf = (c > 0)   ? base[rp - 1] : 0.0f;
                float rt = (c < 124) ? base[rp + 4] : 0.0f;
                o6[0] = lf  + 10.0f; o6[1] = v.x + 10.0f; o6[2] = v.y + 10.0f;
                o6[3] = v.z + 10.0f; o6[4] = v.w + 10.0f; o6[5] = rt  + 10.0f;
            }
            {   // south row gr+1
                size_t rp = (size_t)(rin ? gr + 1 : gr) * 128 + c;
                float4 v = *(const float4*)(base + rp);
                float lf = (c > 0)   ? base[rp - 1] : 0.0f;
                float rt = (c < 124) ? base[rp + 4] : 0.0f;
                if (!rin) { v = make_float4(0,0,0,0); lf = 0.0f; rt = 0.0f; }
                s6[0] = lf  + 10.0f; s6[1] = v.x + 10.0f; s6[2] = v.y + 10.0f;
                s6[3] = v.z + 10.0f; s6[4] = v.w + 10.0f; s6[5] = rt  + 10.0f;
            }
            {   // W weight of px0 (pair with left-neighbor pixel)
                float dW = o6[0] - o6[1];
                if (ch == 0) sW0 = dW * dW; else sW0 = fmaf(dW, dW, sW0);
            }
            #pragma unroll
            for (int j = 0; j < 4; ++j) {
                float cc  = o6[1 + j];
                float dE  = o6[2 + j] - cc;
                float dS  = s6[1 + j] - cc;
                float dSE = s6[2 + j] - cc;
                float dSW = s6[j]     - cc;
                if (ch == 0) {
                    sE[j]=dE*dE; sS[j]=dS*dS; sSEa[j]=dSE*dSE; sSWa[j]=dSW*dSW;
                } else {
                    sE[j]=fmaf(dE,dE,sE[j]);    sS[j]=fmaf(dS,dS,sS[j]);
                    sSEa[j]=fmaf(dSE,dSE,sSEa[j]); sSWa[j]=fmaf(dSW,dSW,sSWa[j]);
                }
            }
        }
        const float sp1 = 1.0f / 1800.0f;
        const float sp2 = 2.0f / 1800.0f;
        bool hB = rin;
        #pragma unroll
        for (int j = 0; j < 4; ++j) {
            int w = c + j;
            bool hL = (w > 0), hR = (w < 127);
            float v;
            v = 3.0f * expf(-sE[j]  * 2.0f - sp1); wE[j]  = hR        ? v : 0.0f;
            v = 3.0f * expf(-sS[j]  * 2.0f - sp1); wS[j]  = hB        ? v : 0.0f;
            v = 3.0f * expf(-sSEa[j]* 2.0f - sp2); wSE[j] = (hB && hR)? v : 0.0f;
            v = 3.0f * expf(-sSWa[j]* 2.0f - sp2); wSW[j] = (hB && hL)? v : 0.0f;
        }
        {
            float v = 3.0f * expf(-sW0 * 2.0f - sp1);
            wW0 = (c > 0) ? v : 0.0f;
        }
    }

    cluster_sync_();   // all smem zeroed cluster-wide before any plane/state write

    // ---- publish S/SE/SW into planes (row q = tr+1) + boundary push ----
    {
        int q = (tr + 1) * W136 + 4 + c;
        *(float4*)(pS  + q) = make_float4(wS[0],  wS[1],  wS[2],  wS[3]);
        *(float4*)(pSE + q) = make_float4(wSE[0], wSE[1], wSE[2], wSE[3]);
        *(float4*)(pSW + q) = make_float4(wSW[0], wSW[1], wSW[2], wSW[3]);
        if (tr == RPC - 1 && r < CL - 1) {   // neighbor's plane row 0
            uint32_t aS  = (uint32_t)__cvta_generic_to_shared(pS  + 4 + c);
            uint32_t aSE = (uint32_t)__cvta_generic_to_shared(pSE + 4 + c);
            uint32_t aSW = (uint32_t)__cvta_generic_to_shared(pSW + 4 + c);
            #pragma unroll
            for (int i = 0; i < 4; ++i) {
                st_peer(aS  + 4u * i, r + 1u, wS[i]);
                st_peer(aSE + 4u * i, r + 1u, wSE[i]);
                st_peer(aSW + 4u * i, r + 1u, wSW[i]);
            }
        }
    }

    // ---- init states (+-1) and target bits ----
    bool sndUp = (tr == 0)       && (r > 0);
    bool sndDn = (tr == RPC - 1) && (r < CL - 1);
    unsigned tb = 0, curmask = 0;
    {
        float4 xa = *(const float4*)(x + gp);
        float4 ta = *(const float4*)(tg + gp);
        float xs[4] = {xa.x, xa.y, xa.z, xa.w};
        float ts[4] = {ta.x, ta.y, ta.z, ta.w};
        float sig[4];
        #pragma unroll
        for (int i = 0; i < 4; ++i) {
            if (ts[i] > 0.5f) tb |= (1u << i);
            bool on = (xs[i] * ts[i] > 0.5f);
            if (on) curmask |= (1u << i);
            sig[i] = on ? 1.0f : -1.0f;
        }
        *(float4*)(st0 + so) = make_float4(sig[0], sig[1], sig[2], sig[3]);
        if (sndUp) {
            uint32_t la = (uint32_t)__cvta_generic_to_shared(st0 + (RPC + 1) * W136 + 4 + c);
            #pragma unroll
            for (int i = 0; i < 4; ++i) st_peer(la + 4u * i, r - 1u, sig[i]);
        }
        if (sndDn) {
            uint32_t la = (uint32_t)__cvta_generic_to_shared(st0 + 4 + c);
            #pragma unroll
            for (int i = 0; i < 4; ++i) st_peer(la + 4u * i, r + 1u, sig[i]);
        }
    }
    cluster_sync_();   // planes + initial states visible cluster-wide

    // ---- fetch mirrored N/NW/NE weights from plane row tr ----
    float wN[4], wNW[4], wNE[4];
    {
        int qN = tr * W136 + 4 + c;
        float4 n4 = *(const float4*)(pS + qN);
        wN[0] = n4.x; wN[1] = n4.y; wN[2] = n4.z; wN[3] = n4.w;
        float4 se4 = *(const float4*)(pSE + qN);
        float seL = pSE[qN - 1];
        wNW[0] = seL;  wNW[1] = se4.x; wNW[2] = se4.y; wNW[3] = se4.z;
        float4 sw4 = *(const float4*)(pSW + qN);
        float swR = pSW[qN + 4];
        wNE[0] = sw4.y; wNE[1] = sw4.z; wNE[2] = sw4.w; wNE[3] = swR;
    }

    const float* A = st0;
    float* B = st1;
    for (int it = 0; it < 10; ++it) {
        const float* Ar = A + so;
        float acc[4];
        {   // mid row: center + E + W  (wW[j] == wE[j-1] for j>=1)
            float4 m4 = *(const float4*)(Ar);
            float lm = Ar[-1], rm = Ar[4];
            float mw[6] = {lm, m4.x, m4.y, m4.z, m4.w, rm};
            #pragma unroll
            for (int j = 0; j < 4; ++j) {
                float wWj = (j == 0) ? wW0 : wE[j - 1];
                float a = 3.0f * mw[j + 1];
                a += wE[j] * mw[j + 2];
                a += wWj   * mw[j];
                acc[j] = a;
            }
        }
        {   // top row: N + NW + NE
            float4 u4 = *(const float4*)(Ar - W136);
            float lu = Ar[-W136 - 1], ru = Ar[-W136 + 4];
            float tw[6] = {lu, u4.x, u4.y, u4.z, u4.w, ru};
            #pragma unroll
            for (int j = 0; j < 4; ++j) {
                float a = acc[j];
                a += wN[j]  * tw[j + 1];
                a += wNW[j] * tw[j];
                a += wNE[j] * tw[j + 2];
                acc[j] = a;
            }
        }
        {   // bottom row: S + SE + SW
            float4 d4 = *(const float4*)(Ar + W136);
            float ld = Ar[W136 - 1], rd = Ar[W136 + 4];
            float bw[6] = {ld, d4.x, d4.y, d4.z, d4.w, rd};
            #pragma unroll
            for (int j = 0; j < 4; ++j) {
                float a = acc[j];
                a += wS[j]  * bw[j + 1];
                a += wSE[j] * bw[j + 2];
                a += wSW[j] * bw[j];
                acc[j] = a;
            }
        }
        unsigned nm = 0;
        #pragma unroll
        for (int j = 0; j < 4; ++j)
            if (acc[j] > 0.0f && ((tb >> j) & 1u)) nm |= (1u << j);
        curmask = nm;
        if (it == 9) break;

        float sig[4];
        #pragma unroll
        for (int i = 0; i < 4; ++i)
            sig[i] = ((nm >> i) & 1u) ? 1.0f : -1.0f;
        *(float4*)(B + so) = make_float4(sig[0], sig[1], sig[2], sig[3]);
        if (sndUp) {
            uint32_t la = (uint32_t)__cvta_generic_to_shared(B + (RPC + 1) * W136 + 4 + c);
            #pragma unroll
            for (int i = 0; i < 4; ++i) st_peer(la + 4u * i, r - 1u, sig[i]);
        }
        if (sndDn) {
            uint32_t la = (uint32_t)__cvta_generic_to_shared(B + 4 + c);
            #pragma unroll
            for (int i = 0; i < 4; ++i) st_peer(la + 4u * i, r + 1u, sig[i]);
        }
        cluster_sync_();   // release/acquire: orders all smem writes cluster-wide
        const float* tmp = A; A = B; B = (float*)tmp;
    }

    // ---- final outputs ----
    float o[4];
    #pragma unroll
    for (int i = 0; i < 4; ++i) o[i] = ((curmask >> i) & 1u) ? 1.0f : 0.0f;
    *(float4*)(out_masks + gp) = make_float4(o[0], o[1], o[2], o[3]);

    // ---- fused valid ----
    unsigned p = __popc(curmask);
    #pragma unroll
    for (int off = 16; off; off >>= 1) p += __shfl_down_sync(0xffffffffu, p, off);
    if (lane == 0) red2[t >> 5] = (int)p;
    __syncthreads();
    if (t < 32) {
        int v = red2[t];
        #pragma unroll
        for (int off = 16; off; off >>= 1) v += __shfl_down_sync(0xffffffffu, v, off);
        if (t == 0) {
            int ret = atomicAdd(&g_cnt[b], v + (1 << 20));
            int tot = ret + v + (1 << 20);
            if ((tot >> 20) == CL) {
                float cfl = (float)(tot & 0xFFFFF);
                out_valid[b] = (cfl >= 16384.0f * 0.05f && cfl <= 16384.0f * 0.95f)
                               ? 1.0f : 0.0f;
            }
        }
    }
}

// ================= launch =================

extern "C" void kernel_launch(void* const* d_in, const int* in_sizes, int n_in,
                              void* d_out, int out_size) {
    const float* seg_masks   = (const float*)d_in[0];
    const float* cate_scores = (const float*)d_in[1];
    const float* feature_map = (const float*)d_in[2];
    const float* x           = (const float*)d_in[3];
    const float* targets     = (const float*)d_in[4];
    const int*   cate_labels = (const int*)d_in[5];

    float* out_scores = (float*)d_out;                  // [256]
    float* out_masks  = out_scores + NMS_N;             // [64*128*128]
    float* out_valid  = out_masks + NPIX;               // [64]

    static cudaStream_t s2 = nullptr;
    static cudaEvent_t evFork = nullptr, evJoin = nullptr;
    if (s2 == nullptr) {
        cudaStreamCreateWithFlags(&s2, cudaStreamNonBlocking);
        cudaEventCreateWithFlags(&evFork, cudaEventDisableTiming);
        cudaEventCreateWithFlags(&evJoin, cudaEventDisableTiming);
    }

    // ---- fork: NMS chain on s2, CRF on the main stream ----
    cudaEventRecord(evFork, 0);
    cudaStreamWaitEvent(s2, evFork, 0);

    pack_kernel<<<NMS_N, 512, 0, s2>>>(seg_masks);
    nms_iou_kernel<<<NMS_N, NMS_N, 0, s2>>>(cate_labels);
    nms_coef_kernel<<<NMS_N, NMS_N, 0, s2>>>(cate_scores, out_scores);
    cudaEventRecord(evJoin, s2);

    cudaFuncSetAttribute(crf_persistent, cudaFuncAttributeMaxDynamicSharedMemorySize,
                         SMF * (int)sizeof(float));
    crf_persistent<<<CL * NB, NTHR, SMF * sizeof(float)>>>(feature_map, x, targets,
                                                           out_masks, out_valid);

    // ---- join ----
    cudaStreamWaitEvent(0, evJoin, 0);
}